// round 2
// baseline (speedup 1.0000x reference)
#include <cuda_runtime.h>
#include <math_constants.h>

// Problem constants (fixed by the dataset).
#define NPTS   100000
#define DIM    512
#define NQ     2048
#define TOPK   5
#define SPLIT  18
#define SLICE  ((NPTS + SPLIT - 1) / SPLIT)   // 5556
#define TM     128
#define TN     128
#define TK     8
#define SC_STRIDE 132                         // padded to break bank conflicts on row scans

// Scratch (allocation-free contract: __device__ globals only).
__device__ float g_x2[NPTS];
__device__ float g_vals[(size_t)NQ * SPLIT * TOPK];
__device__ int   g_idx [(size_t)NQ * SPLIT * TOPK];

// ---------------------------------------------------------------------------
// x2[n] = ||X[n]||^2  (one warp per point, float4 loads, warp reduce)
// ---------------------------------------------------------------------------
__global__ void x2_kernel(const float* __restrict__ X) {
    int warp = (blockIdx.x * blockDim.x + threadIdx.x) >> 5;
    int lane = threadIdx.x & 31;
    if (warp >= NPTS) return;
    const float4* row = (const float4*)(X + (size_t)warp * DIM);
    float s = 0.f;
#pragma unroll
    for (int i = 0; i < DIM / 4 / 32; ++i) {
        float4 v = row[lane + i * 32];
        s += v.x * v.x + v.y * v.y + v.z * v.z + v.w * v.w;
    }
#pragma unroll
    for (int o = 16; o; o >>= 1) s += __shfl_xor_sync(0xffffffffu, s, o);
    if (lane == 0) g_x2[warp] = s;
}

// ---------------------------------------------------------------------------
// Fused distance-GEMM + per-slice top-5.
// grid = (NQ/TM, SPLIT). Each block: 128 queries x one N-slice.
// score(q,n) = 2*dot(q,x_n) - ||x_n||^2   (q^2 is row-constant -> dropped)
// ---------------------------------------------------------------------------
__global__ __launch_bounds__(256, 2) void knn_main(
    const float* __restrict__ Q, const float* __restrict__ X)
{
    extern __shared__ float smem[];
    float* As  = smem;                       // 2 x TK x TM = 2048 floats
    float* Bs  = smem + 2048;                // 2048 floats
    float* Sc  = smem + 4096;                // TM x SC_STRIDE
    float* x2s = smem + 4096 + TM * SC_STRIDE;

    const int tid = threadIdx.x;
    const int tx = tid & 15, ty = tid >> 4;
    const int qbase  = blockIdx.x * TM;
    const int nStart = blockIdx.y * SLICE;
    const int nEnd   = min(nStart + SLICE, NPTS);

    // thread r (<128) owns the sorted top-5 of query row r
    float bv[TOPK]; int bi[TOPK];
#pragma unroll
    for (int s = 0; s < TOPK; ++s) { bv[s] = -CUDART_INF_F; bi[s] = 0; }

    const int lrow = tid >> 1;        // 0..127
    const int lk   = (tid & 1) * 4;   // 0 or 4

    const float* Aptr = Q + (size_t)(qbase + lrow) * DIM + lk;

    for (int nTile = nStart; nTile < nEnd; nTile += TN) {
        if (tid < TN) {
            int n = nTile + tid;
            x2s[tid] = (n < nEnd) ? g_x2[n] : 0.f;
        }

        float acc[8][8];
#pragma unroll
        for (int i = 0; i < 8; ++i)
#pragma unroll
            for (int j = 0; j < 8; ++j) acc[i][j] = 0.f;

        const int  xrow  = nTile + lrow;
        const bool bvld  = xrow < NPTS;
        const float* Bptr = X + (size_t)xrow * DIM + lk;

        // prologue: chunk 0
        float4 ra = *(const float4*)Aptr;
        float4 rb = bvld ? *(const float4*)Bptr : make_float4(0, 0, 0, 0);
        int buf = 0;
        {
            float* a = As + lk * TM + lrow;
            a[0] = ra.x; a[TM] = ra.y; a[2 * TM] = ra.z; a[3 * TM] = ra.w;
            float* b = Bs + lk * TN + lrow;
            b[0] = rb.x; b[TN] = rb.y; b[2 * TN] = rb.z; b[3 * TN] = rb.w;
        }
        __syncthreads();   // also covers x2s load

#pragma unroll 1
        for (int kc = 0; kc < DIM / TK; ++kc) {
            if (kc + 1 < DIM / TK) {
                ra = *(const float4*)(Aptr + (kc + 1) * TK);
                rb = bvld ? *(const float4*)(Bptr + (kc + 1) * TK)
                          : make_float4(0, 0, 0, 0);
            }
            const float* a_s = As + buf * (TK * TM);
            const float* b_s = Bs + buf * (TK * TN);
#pragma unroll
            for (int kk = 0; kk < TK; ++kk) {
                float a[8], b[8];
                float4 t0 = *(const float4*)(a_s + kk * TM + ty * 8);
                float4 t1 = *(const float4*)(a_s + kk * TM + ty * 8 + 4);
                a[0] = t0.x; a[1] = t0.y; a[2] = t0.z; a[3] = t0.w;
                a[4] = t1.x; a[5] = t1.y; a[6] = t1.z; a[7] = t1.w;
                float4 u0 = *(const float4*)(b_s + kk * TN + tx * 8);
                float4 u1 = *(const float4*)(b_s + kk * TN + tx * 8 + 4);
                b[0] = u0.x; b[1] = u0.y; b[2] = u0.z; b[3] = u0.w;
                b[4] = u1.x; b[5] = u1.y; b[6] = u1.z; b[7] = u1.w;
#pragma unroll
                for (int i = 0; i < 8; ++i)
#pragma unroll
                    for (int j = 0; j < 8; ++j)
                        acc[i][j] = fmaf(a[i], b[j], acc[i][j]);
            }
            if (kc + 1 < DIM / TK) {
                buf ^= 1;
                float* a = As + buf * (TK * TM) + lk * TM + lrow;
                a[0] = ra.x; a[TM] = ra.y; a[2 * TM] = ra.z; a[3 * TM] = ra.w;
                float* b = Bs + buf * (TK * TN) + lk * TN + lrow;
                b[0] = rb.x; b[TN] = rb.y; b[2 * TN] = rb.z; b[3 * TN] = rb.w;
                __syncthreads();
            }
        }

        // epilogue: scores -> smem, then per-row top-5 update
#pragma unroll
        for (int i = 0; i < 8; ++i) {
            int row = ty * 8 + i;
#pragma unroll
            for (int j = 0; j < 8; ++j) {
                int col = tx * 8 + j;
                bool ok = (nTile + col) < nEnd;
                Sc[row * SC_STRIDE + col] =
                    ok ? 2.f * acc[i][j] - x2s[col] : -CUDART_INF_F;
            }
        }
        __syncthreads();

        if (tid < TM) {
#pragma unroll 4
            for (int c = 0; c < TN; ++c) {
                float v = Sc[tid * SC_STRIDE + c];
                if (v > bv[TOPK - 1]) {
                    bv[TOPK - 1] = v; bi[TOPK - 1] = nTile + c;
#pragma unroll
                    for (int s = TOPK - 1; s > 0; --s) {
                        if (bv[s] > bv[s - 1]) {
                            float tv = bv[s]; bv[s] = bv[s - 1]; bv[s - 1] = tv;
                            int   ti = bi[s]; bi[s] = bi[s - 1]; bi[s - 1] = ti;
                        }
                    }
                }
            }
        }
        __syncthreads();   // before Sc / x2s / As / Bs are overwritten
    }

    if (tid < TM) {
        int q = qbase + tid;
        size_t base = ((size_t)q * SPLIT + blockIdx.y) * TOPK;
#pragma unroll
        for (int s = 0; s < TOPK; ++s) { g_vals[base + s] = bv[s]; g_idx[base + s] = bi[s]; }
    }
}

// ---------------------------------------------------------------------------
// Merge per-slice candidates, gather labels, write [B,2] padded output.
// NOTE: Y arrives as int32 — JAX's default x64-disable downgrades the
// reference's jnp.int64 to int32 silently.
// ---------------------------------------------------------------------------
__global__ void knn_merge(const int* __restrict__ Y, float* __restrict__ out) {
    int q = blockIdx.x * blockDim.x + threadIdx.x;
    if (q >= NQ) return;
    float bv[TOPK]; int bi[TOPK];
#pragma unroll
    for (int s = 0; s < TOPK; ++s) { bv[s] = -CUDART_INF_F; bi[s] = 0; }
    size_t base = (size_t)q * SPLIT * TOPK;
    for (int c = 0; c < SPLIT * TOPK; ++c) {
        float v = g_vals[base + c];
        if (v > bv[TOPK - 1]) {
            int id = g_idx[base + c];
            bv[TOPK - 1] = v; bi[TOPK - 1] = id;
#pragma unroll
            for (int s = TOPK - 1; s > 0; --s) {
                if (bv[s] > bv[s - 1]) {
                    float tv = bv[s]; bv[s] = bv[s - 1]; bv[s - 1] = tv;
                    int   ti = bi[s]; bi[s] = bi[s - 1]; bi[s - 1] = ti;
                }
            }
        }
    }
    float s = 0.f;
#pragma unroll
    for (int k = 0; k < TOPK; ++k) s += (float)Y[bi[k]];
    out[q * 2 + 0] = s * (1.0f / TOPK);
    out[q * 2 + 1] = 0.f;
}

// ---------------------------------------------------------------------------
extern "C" void kernel_launch(void* const* d_in, const int* in_sizes, int n_in,
                              void* d_out, int out_size) {
    const float* Qm = (const float*)d_in[0];
    const float* X  = (const float*)d_in[1];
    const int*   Y  = (const int*)d_in[2];
    float* out = (float*)d_out;

    cudaFuncSetAttribute(knn_main, cudaFuncAttributeMaxDynamicSharedMemorySize,
                         96 * 1024);

    x2_kernel<<<(NPTS + 7) / 8, 256>>>(X);

    dim3 grid(NQ / TM, SPLIT);
    size_t smem = (size_t)(4096 + TM * SC_STRIDE + TM) * sizeof(float);
    knn_main<<<grid, 256, smem>>>(Qm, X);

    knn_merge<<<(NQ + 255) / 256, 256>>>(Y, out);
}

// round 5
// speedup vs baseline: 2.5062x; 2.5062x over previous
#include <cuda_runtime.h>
#include <cuda_bf16.h>
#include <math_constants.h>
#include <cstdint>

// ---------------- problem constants ----------------
#define NPTS 100000
#define DIM  512
#define NQ   2048
#define TOPK 5
#define TM   128
#define TN   128
#define KCH  32                 // K chunk (elements)
#define NCHK (DIM / KCH)        // 16
#define SPLIT 9
#define SLICE 11136             // 87 tiles * 128;  9*11136 >= NPTS
#define RS   80                 // smem row stride bytes (64B data + 16B pad)
#define SZT  (128 * RS)         // 10240 bytes per (operand-half, buffer)

// smem byte offsets
#define OFF_SC   0                       // scores 128 x 132 f32 = 67584
#define OFF_X2S  67584                   // 128 f32 (pad to 512)
#define OFF_AH   68096                   // 2 bufs
#define OFF_AL   (OFF_AH + 2 * SZT)      // 88576
#define OFF_BH   (OFF_AL + 2 * SZT)     // 109056
#define OFF_BL   (OFF_BH + 2 * SZT)     // 129536
#define SMEM_TOT (OFF_BL + 2 * SZT)     // 150016
#define DLO      (2 * SZT)               // hi->lo delta (20480)

// ---------------- scratch ----------------
__device__ float g_x2[NPTS];
__device__ float g_vals[(size_t)NQ * SPLIT * TOPK];
__device__ int   g_idx [(size_t)NQ * SPLIT * TOPK];

// ---------------- helpers ----------------
__device__ __forceinline__ uint32_t smem_u32(const void* p) {
    uint32_t a;
    asm("{ .reg .u64 t; cvta.to.shared.u64 t, %1; cvt.u32.u64 %0, t; }" : "=r"(a) : "l"(p));
    return a;
}
__device__ __forceinline__ uint32_t pack2(float lo, float hi) {
    uint32_t r;  // upper half <- %1 (hi), lower half <- %2 (lo)
    asm("cvt.rn.bf16x2.f32 %0, %1, %2;" : "=r"(r) : "f"(hi), "f"(lo));
    return r;
}
#define LDSM4(R0, R1, R2, R3, ADDR)                                          \
    asm volatile("ldmatrix.sync.aligned.m8n8.x4.shared.b16 {%0,%1,%2,%3}, [%4];" \
                 : "=r"(R0), "=r"(R1), "=r"(R2), "=r"(R3) : "r"(ADDR))
#define MMA(C, A, B0, B1)                                                    \
    asm volatile("mma.sync.aligned.m16n8k16.row.col.f32.bf16.bf16.f32 "     \
                 "{%0,%1,%2,%3}, {%4,%5,%6,%7}, {%8,%9}, {%0,%1,%2,%3};"    \
                 : "+f"((C)[0]), "+f"((C)[1]), "+f"((C)[2]), "+f"((C)[3])   \
                 : "r"((A)[0]), "r"((A)[1]), "r"((A)[2]), "r"((A)[3]),      \
                   "r"(B0), "r"(B1))

// fp32x4 -> (hi,lo) bf16x4, stored unswizzled at padded stride RS.
__device__ __forceinline__ void split_store(char* hiB, char* loB, int row, int k4, float4 v) {
    uint32_t h01 = pack2(v.x, v.y);
    uint32_t h23 = pack2(v.z, v.w);
    float f0 = __uint_as_float(h01 << 16);
    float f1 = __uint_as_float(h01 & 0xFFFF0000u);
    float f2 = __uint_as_float(h23 << 16);
    float f3 = __uint_as_float(h23 & 0xFFFF0000u);
    uint32_t l01 = pack2(v.x - f0, v.y - f1);
    uint32_t l23 = pack2(v.z - f2, v.w - f3);
    int off = row * RS + k4 * 8;
    *(uint2*)(hiB + off) = make_uint2(h01, h23);
    *(uint2*)(loB + off) = make_uint2(l01, l23);
}

__device__ __forceinline__ void top5_ins(float v, int n, float bv[TOPK], int bi[TOPK]) {
    if (v > bv[TOPK - 1]) {
        bv[TOPK - 1] = v; bi[TOPK - 1] = n;
#pragma unroll
        for (int s = TOPK - 1; s > 0; --s) {
            if (bv[s] > bv[s - 1]) {
                float tv = bv[s]; bv[s] = bv[s - 1]; bv[s - 1] = tv;
                int   ti = bi[s]; bi[s] = bi[s - 1]; bi[s - 1] = ti;
            }
        }
    }
}

// ---------------------------------------------------------------------------
__global__ void x2_kernel(const float* __restrict__ X) {
    int warp = (blockIdx.x * blockDim.x + threadIdx.x) >> 5;
    int lane = threadIdx.x & 31;
    if (warp >= NPTS) return;
    const float4* row = (const float4*)(X + (size_t)warp * DIM);
    float s = 0.f;
#pragma unroll
    for (int i = 0; i < DIM / 4 / 32; ++i) {
        float4 v = row[lane + i * 32];
        s += v.x * v.x + v.y * v.y + v.z * v.z + v.w * v.w;
    }
#pragma unroll
    for (int o = 16; o; o >>= 1) s += __shfl_xor_sync(0xffffffffu, s, o);
    if (lane == 0) g_x2[warp] = s;
}

// ---------------------------------------------------------------------------
// bf16-split HMMA distance GEMM + fused per-slice top-5.
// grid = (16, SPLIT), 256 threads (8 warps, 2x4 warp grid, 64x32 warp tile).
// ---------------------------------------------------------------------------
__global__ __launch_bounds__(256, 1) void knn_main(
    const float* __restrict__ Q, const float* __restrict__ X)
{
    extern __shared__ char sm[];
    const uint32_t sb = smem_u32(sm);
    float* Sc  = (float*)(sm + OFF_SC);
    float* x2s = (float*)(sm + OFF_X2S);

    const int tid = threadIdx.x, wid = tid >> 5, lane = tid & 31;
    const int m_off = (wid & 1) * 64;
    const int n_off = (wid >> 1) * 32;
    const int qbase  = blockIdx.x * TM;
    const int nStart = blockIdx.y * SLICE;
    const int nEnd   = min(nStart + SLICE, NPTS);

    // ldmatrix per-thread address offsets (within an operand tile)
    const uint32_t aoff = (uint32_t)(m_off + (lane & 15)) * RS + ((lane >> 4) << 4);
    const uint32_t boff = (uint32_t)(n_off + (lane & 7) + ((lane >> 4) << 3)) * RS
                        + (((lane >> 3) & 1) << 4);

    // global-load mapping: thread covers rows (tid>>3)+i*32, k4 = tid&7
    const int rBase = tid >> 3;
    const int k4    = tid & 7;
    const float* aGlob = Q + (size_t)(qbase + rBase) * DIM + k4 * 4;

    float bv[TOPK]; int bi[TOPK];
#pragma unroll
    for (int s = 0; s < TOPK; ++s) { bv[s] = -CUDART_INF_F; bi[s] = 0; }

#pragma unroll 1
    for (int nTile = nStart; nTile < nEnd; nTile += TN) {
        const int colLim = min(TN, nEnd - nTile);

        if (tid < 128) {
            int n = nTile + tid;
            x2s[tid] = (n < nEnd) ? g_x2[n] : 0.f;
        }

        float acc[4][4][4];
#pragma unroll
        for (int mi = 0; mi < 4; ++mi)
#pragma unroll
            for (int ni = 0; ni < 4; ++ni)
#pragma unroll
                for (int r = 0; r < 4; ++r) acc[mi][ni][r] = 0.f;

        float4 ra[4], rb[4];
        // ---- prologue: chunk 0 -> buf 0 ----
#pragma unroll
        for (int i = 0; i < 4; ++i)
            ra[i] = *(const float4*)(aGlob + (size_t)i * 32 * DIM);
#pragma unroll
        for (int i = 0; i < 4; ++i) {
            int xr = nTile + rBase + i * 32;
            rb[i] = (xr < NPTS) ? *(const float4*)(X + (size_t)xr * DIM + k4 * 4)
                                : make_float4(0.f, 0.f, 0.f, 0.f);
        }
#pragma unroll
        for (int i = 0; i < 4; ++i) {
            split_store(sm + OFF_AH, sm + OFF_AL, rBase + i * 32, k4, ra[i]);
            split_store(sm + OFF_BH, sm + OFF_BL, rBase + i * 32, k4, rb[i]);
        }
        __syncthreads();

        int buf = 0;
#pragma unroll 1
        for (int c = 0; c < NCHK; ++c) {
            if (c + 1 < NCHK) {
#pragma unroll
                for (int i = 0; i < 4; ++i)
                    ra[i] = *(const float4*)(aGlob + (c + 1) * KCH + (size_t)i * 32 * DIM);
#pragma unroll
                for (int i = 0; i < 4; ++i) {
                    int xr = nTile + rBase + i * 32;
                    rb[i] = (xr < NPTS)
                        ? *(const float4*)(X + (size_t)xr * DIM + (c + 1) * KCH + k4 * 4)
                        : make_float4(0.f, 0.f, 0.f, 0.f);
                }
            }

            const uint32_t sAH = sb + OFF_AH + buf * SZT;
            const uint32_t sBH = sb + OFF_BH + buf * SZT;
#pragma unroll
            for (int s = 0; s < 2; ++s) {           // two k16 steps per chunk
                uint32_t ah[4][4], al[4][4], bh[4][2], bl[4][2];
#pragma unroll
                for (int mi = 0; mi < 4; ++mi) {
                    uint32_t adr = sAH + aoff + mi * (16 * RS) + s * 32;
                    LDSM4(ah[mi][0], ah[mi][1], ah[mi][2], ah[mi][3], adr);
                    LDSM4(al[mi][0], al[mi][1], al[mi][2], al[mi][3], adr + DLO);
                }
#pragma unroll
                for (int nj = 0; nj < 2; ++nj) {
                    uint32_t adr = sBH + boff + nj * (16 * RS) + s * 32;
                    uint32_t r0, r1, r2, r3;
                    LDSM4(r0, r1, r2, r3, adr);
                    bh[2 * nj][0] = r0; bh[2 * nj][1] = r1;
                    bh[2 * nj + 1][0] = r2; bh[2 * nj + 1][1] = r3;
                    LDSM4(r0, r1, r2, r3, adr + DLO);
                    bl[2 * nj][0] = r0; bl[2 * nj][1] = r1;
                    bl[2 * nj + 1][0] = r2; bl[2 * nj + 1][1] = r3;
                }
#pragma unroll
                for (int mi = 0; mi < 4; ++mi)
#pragma unroll
                    for (int ni = 0; ni < 4; ++ni) {
                        MMA(acc[mi][ni], ah[mi], bh[ni][0], bh[ni][1]);
                        MMA(acc[mi][ni], ah[mi], bl[ni][0], bl[ni][1]);
                        MMA(acc[mi][ni], al[mi], bh[ni][0], bh[ni][1]);
                    }
            }

            if (c + 1 < NCHK) {
                char* hA = sm + OFF_AH + (buf ^ 1) * SZT;
                char* lA = sm + OFF_AL + (buf ^ 1) * SZT;
                char* hB = sm + OFF_BH + (buf ^ 1) * SZT;
                char* lB = sm + OFF_BL + (buf ^ 1) * SZT;
#pragma unroll
                for (int i = 0; i < 4; ++i) {
                    split_store(hA, lA, rBase + i * 32, k4, ra[i]);
                    split_store(hB, lB, rBase + i * 32, k4, rb[i]);
                }
            }
            __syncthreads();
            buf ^= 1;
        }

        // ---- epilogue: acc -> Sc (with 2*dot - x2), then row scans ----
        {
            const int rlo = lane >> 2;
            const int cl  = (lane & 3) * 2;
#pragma unroll
            for (int mi = 0; mi < 4; ++mi) {
#pragma unroll
                for (int ni = 0; ni < 4; ++ni) {
                    int col = n_off + ni * 8 + cl;
                    float2 x2p = *(float2*)&x2s[col];
                    int r0 = m_off + mi * 16 + rlo;
                    float2 v0 = make_float2(2.f * acc[mi][ni][0] - x2p.x,
                                            2.f * acc[mi][ni][1] - x2p.y);
                    float2 v1 = make_float2(2.f * acc[mi][ni][2] - x2p.x,
                                            2.f * acc[mi][ni][3] - x2p.y);
                    *(float2*)&Sc[r0 * 132 + col] = v0;
                    *(float2*)&Sc[(r0 + 8) * 132 + col] = v1;
                }
            }
        }
        __syncthreads();

        if (tid < 128) {
#pragma unroll 4
            for (int c = 0; c < colLim; ++c) {
                float v = Sc[tid * 132 + c];
                top5_ins(v, nTile + c, bv, bi);
            }
        }
        __syncthreads();
    }

    if (tid < 128) {
        int q = qbase + tid;
        size_t base = ((size_t)q * SPLIT + blockIdx.y) * TOPK;
#pragma unroll
        for (int s = 0; s < TOPK; ++s) { g_vals[base + s] = bv[s]; g_idx[base + s] = bi[s]; }
    }
}

// ---------------------------------------------------------------------------
__global__ void knn_merge(const int* __restrict__ Y, float* __restrict__ out) {
    int q = blockIdx.x * blockDim.x + threadIdx.x;
    if (q >= NQ) return;
    float bv[TOPK]; int bi[TOPK];
#pragma unroll
    for (int s = 0; s < TOPK; ++s) { bv[s] = -CUDART_INF_F; bi[s] = 0; }
    size_t base = (size_t)q * SPLIT * TOPK;
    for (int c = 0; c < SPLIT * TOPK; ++c) {
        float v = g_vals[base + c];
        if (v > bv[TOPK - 1]) {
            int id = g_idx[base + c];
            bv[TOPK - 1] = v; bi[TOPK - 1] = id;
#pragma unroll
            for (int s = TOPK - 1; s > 0; --s) {
                if (bv[s] > bv[s - 1]) {
                    float tv = bv[s]; bv[s] = bv[s - 1]; bv[s - 1] = tv;
                    int   ti = bi[s]; bi[s] = bi[s - 1]; bi[s - 1] = ti;
                }
            }
        }
    }
    float s = 0.f;
#pragma unroll
    for (int k = 0; k < TOPK; ++k) s += (float)Y[bi[k]];
    out[q * 2 + 0] = s * (1.0f / TOPK);
    out[q * 2 + 1] = 0.f;
}

// ---------------------------------------------------------------------------
extern "C" void kernel_launch(void* const* d_in, const int* in_sizes, int n_in,
                              void* d_out, int out_size) {
    const float* Qm = (const float*)d_in[0];
    const float* X  = (const float*)d_in[1];
    const int*   Y  = (const int*)d_in[2];
    float* out = (float*)d_out;

    cudaFuncSetAttribute(knn_main, cudaFuncAttributeMaxDynamicSharedMemorySize, SMEM_TOT);

    x2_kernel<<<(NPTS + 7) / 8, 256>>>(X);

    dim3 grid(NQ / TM, SPLIT);
    knn_main<<<grid, 256, SMEM_TOT>>>(Qm, X);

    knn_merge<<<(NQ + 255) / 256, 256>>>(Y, out);
}